// round 14
// baseline (speedup 1.0000x reference)
#include <cuda_runtime.h>
#include <cstdint>

#define MAXN 100000
#define MAXE 1250000
#define DH   64
#define CC   40
#define ELLW 40          // ELL width; Poisson(12.5) => P(deg>40) ~ 1e-10
#define OVFCAP 8192

typedef unsigned long long u64;

// ---- packed f32x2 helpers (sm_10x; PTX-only, ptxas won't auto-fuse) ---------
__device__ __forceinline__ u64 pk2(float lo, float hi) {
    u64 r;
    asm("mov.b64 %0, {%1, %2};" : "=l"(r) : "f"(lo), "f"(hi));
    return r;
}
__device__ __forceinline__ void fma2(u64& d, u64 a, u64 b) {
    asm("fma.rn.f32x2 %0, %1, %2, %0;" : "+l"(d) : "l"(a), "l"(b));
}
__device__ __forceinline__ void unpk2(u64 v, float& lo, float& hi) {
    asm("mov.b64 {%0, %1}, %2;" : "=f"(lo), "=f"(hi) : "l"(v));
}

// ---------------- device scratch (static; no runtime allocation) -------------
__device__ __align__(16) float g_dis[MAXN];
__device__ int   g_deg[MAXN];
__device__ __align__(16) int2 g_ell2[(size_t)MAXN * ELLW];  // (idx, dis-bits)
__device__ int2  g_ovf[OVFCAP];
__device__ int   g_ovfn;
__device__ int   g_is64;
__device__ __align__(16) float g_y [(size_t)MAXN * DH];
__device__ __align__(16) float g_h1[(size_t)MAXN * DH];

// ---------------- helpers ----------------------------------------------------
__device__ __forceinline__ int edge_at(const void* ei, long long pos) {
    if (g_is64) return (int)((const long long*)ei)[pos];
    return ((const int*)ei)[pos];
}

// zero deg + overflow counter + int64/int32 detection
__global__ void k_init(const void* ei, int n) {
    int i = blockIdx.x * blockDim.x + threadIdx.x;
    if (i < n) g_deg[i] = 0;
    if (i == 0) {
        g_ovfn = 0;
        const long long* p = (const long long*)ei;
        int ok = 1;
        #pragma unroll
        for (int k = 0; k < 8; k++) {
            long long v = p[k];
            if (v < 0 || v >= (long long)n) ok = 0;
        }
        g_is64 = ok;
    }
}

// single edge pass: deg count + ELL index fill (+ overflow capture)
__global__ void k_fill(const void* ei, int E) {
    int e = blockIdx.x * blockDim.x + threadIdx.x;
    if (e < E) {
        int r = edge_at(ei, (long long)e);
        int c = edge_at(ei, (long long)E + e);
        int pos = atomicAdd(&g_deg[c], 1);
        if (pos < ELLW) {
            g_ell2[(size_t)c * ELLW + pos].x = r;
        } else {
            int k = atomicAdd(&g_ovfn, 1);
            if (k < OVFCAP) g_ovf[k] = make_int2(r, c);
        }
    }
}

__global__ void k_dis(int n) {
    int i = blockIdx.x * blockDim.x + threadIdx.x;
    if (i < n) g_dis[i] = rsqrtf((float)(g_deg[i] + 1));   // +1 = self-loop
}

// attach dis[idx] into each used ELL slot (one random 4B load per edge, once)
__global__ void k_attach(int n) {
    int i = blockIdx.x * blockDim.x + threadIdx.x;         // over n*ELLW slots
    if (i >= n * ELLW) return;
    int node = i / ELLW;
    int slot = i - node * ELLW;
    if (slot < g_deg[node]) {
        int idx = g_ell2[i].x;
        g_ell2[i].y = __float_as_int(__ldg(&g_dis[idx]));
    }
}

// -------- gather-first aggregation: y_i = dis_i*src_i + sum_nbr dis_r*src_r ---
// warp per node, lane owns float2; packed (idx,dis) pairs, int4-vectorized walk.
__global__ void k_agg(const float* __restrict__ src, float* __restrict__ y, int n)
{
    int w = (blockIdx.x * blockDim.x + threadIdx.x) >> 5;
    int lane = threadIdx.x & 31;
    if (w >= n) return;

    const float2* H = (const float2*)src;
    float  dw = g_dis[w];
    float2 v0 = H[(size_t)w * 32 + lane];
    float2 acc;
    acc.x = dw * v0.x;
    acc.y = dw * v0.y;

    const int deg = g_deg[w];
    const int end = deg < ELLW ? deg : ELLW;
    const int2* row = &g_ell2[(size_t)w * ELLW];   // 320B rows, 16B-aligned

    int p = 0;
    for (; p + 3 < end; p += 4) {
        int4 va = __ldg((const int4*)(row + p));       // slots p, p+1
        int4 vb = __ldg((const int4*)(row + p + 2));   // slots p+2, p+3
        float d0 = __int_as_float(va.y);
        float d1 = __int_as_float(va.w);
        float d2 = __int_as_float(vb.y);
        float d3 = __int_as_float(vb.w);
        float2 a = H[(size_t)va.x * 32 + lane];
        float2 b = H[(size_t)va.z * 32 + lane];
        float2 c = H[(size_t)vb.x * 32 + lane];
        float2 d = H[(size_t)vb.z * 32 + lane];
        acc.x = fmaf(d0, a.x, fmaf(d1, b.x, fmaf(d2, c.x, fmaf(d3, d.x, acc.x))));
        acc.y = fmaf(d0, a.y, fmaf(d1, b.y, fmaf(d2, c.y, fmaf(d3, d.y, acc.y))));
    }
    for (; p < end; p++) {
        int2 v = __ldg(row + p);
        float d0 = __int_as_float(v.y);
        float2 a = H[(size_t)v.x * 32 + lane];
        acc.x = fmaf(d0, a.x, acc.x);
        acc.y = fmaf(d0, a.y, acc.y);
    }

    // overflow edges (normally none): only overflowing targets scan the buffer
    if (deg > ELLW) {
        int novf = g_ovfn;
        for (int i = 0; i < novf; i++) {
            int2 rc = g_ovf[i];
            if (rc.y == w) {
                float d0 = g_dis[rc.x];
                float2 a = H[(size_t)rc.x * 32 + lane];
                acc.x = fmaf(d0, a.x, acc.x);
                acc.y = fmaf(d0, a.y, acc.y);
            }
        }
    }

    ((float2*)y)[(size_t)w * 32 + lane] = acc;
}

// ------------- GEMM+finish: h = relu(dis_i * (y @ W) + b), f32x2 core --------
__global__ void k_gemm_h(const float* __restrict__ Y, const float* __restrict__ W,
                         const float* __restrict__ bias, float* __restrict__ out, int n)
{
    __shared__ float  Xs[64 * 64];
    __shared__ float4 Ws[64 * 16];

    const int tx = threadIdx.x, ty = threadIdx.y;
    const int tid = ty * 16 + tx;

    const float4* Wv = (const float4*)W;
    #pragma unroll
    for (int i = 0; i < 4; i++) Ws[tid + i * 256] = Wv[tid + i * 256];

    const int r0 = blockIdx.x * 64;
    #pragma unroll
    for (int i = 0; i < 4; i++) {
        int idx = tid + i * 256;
        int rr = idx >> 4, cc = idx & 15;
        int gr = r0 + rr;
        float4 v = make_float4(0.f, 0.f, 0.f, 0.f);
        if (gr < n) v = ((const float4*)(Y + (size_t)gr * DH))[cc];
        *(float4*)&Xs[rr * 64 + cc * 4] = v;
    }
    __syncthreads();

    u64 a01[4], a23[4];
    #pragma unroll
    for (int i = 0; i < 4; i++) { a01[i] = 0ull; a23[i] = 0ull; }

    #pragma unroll
    for (int k4 = 0; k4 < 16; k4++) {
        float4 xv[4];
        #pragma unroll
        for (int i = 0; i < 4; i++)
            xv[i] = *(const float4*)&Xs[(ty * 4 + i) * 64 + k4 * 4];
        #pragma unroll
        for (int j = 0; j < 4; j++) {
            float4 w = Ws[(k4 * 4 + j) * 16 + tx];
            u64 w01 = pk2(w.x, w.y);
            u64 w23 = pk2(w.z, w.w);
            #pragma unroll
            for (int i = 0; i < 4; i++) {
                float xs = (j == 0) ? xv[i].x : (j == 1) ? xv[i].y : (j == 2) ? xv[i].z : xv[i].w;
                u64 xd = pk2(xs, xs);
                fma2(a01[i], xd, w01);
                fma2(a23[i], xd, w23);
            }
        }
    }

    float4 b = ((const float4*)bias)[tx];
    #pragma unroll
    for (int i = 0; i < 4; i++) {
        int gr = r0 + ty * 4 + i;
        if (gr >= n) continue;
        float s = g_dis[gr];
        float4 a;
        unpk2(a01[i], a.x, a.y);
        unpk2(a23[i], a.z, a.w);
        a.x = fmaxf(fmaf(s, a.x, b.x), 0.f);
        a.y = fmaxf(fmaf(s, a.y, b.y), 0.f);
        a.z = fmaxf(fmaf(s, a.z, b.z), 0.f);
        a.w = fmaxf(fmaf(s, a.w, b.w), 0.f);
        ((float4*)(out + (size_t)gr * DH))[tx] = a;
    }
}

// ---------------- fused classifier, f32x2 core --------------------------------
__global__ void k_cls(const float* __restrict__ x, const float* __restrict__ h1,
                      const float* __restrict__ y2,
                      const float* __restrict__ Wego, const float* __restrict__ bego,
                      const float* __restrict__ Wc1,  const float* __restrict__ bc1,
                      const float* __restrict__ Wcls, const float* __restrict__ bcls,
                      float* __restrict__ out, int n)
{
    __shared__ float  Xs[64 * 68];     // 17408 B
    __shared__ float4 Wcs[192 * 10];   // 30720 B

    const int tx = threadIdx.x, ty = threadIdx.y;
    const int tid = ty * 16 + tx;
    const int r0 = blockIdx.x * 64;

    const float4* Wclsv = (const float4*)Wcls;
    #pragma unroll
    for (int i = tid; i < 1920; i += 256) Wcs[i] = Wclsv[i];

    u64 c01[4], c23[4];
    #pragma unroll
    for (int i = 0; i < 4; i++) { c01[i] = 0ull; c23[i] = 0ull; }

    auto load_tile = [&](const float* S) {
        #pragma unroll
        for (int i = 0; i < 4; i++) {
            int idx = tid + i * 256;
            int rr = idx >> 4, cc = idx & 15;
            int gr = r0 + rr;
            float4 v = make_float4(0.f, 0.f, 0.f, 0.f);
            if (gr < n) v = ((const float4*)(S + (size_t)gr * DH))[cc];
            *(float4*)&Xs[rr * 68 + cc * 4] = v;
        }
    };

    auto transform = [&](const float* W, const float* bias, bool use_dis) {
        const float4* Wv = (const float4*)W;
        u64 t01[4], t23[4];
        #pragma unroll
        for (int i = 0; i < 4; i++) { t01[i] = 0ull; t23[i] = 0ull; }
        #pragma unroll
        for (int k4 = 0; k4 < 16; k4++) {
            float4 xv[4];
            #pragma unroll
            for (int i = 0; i < 4; i++)
                xv[i] = *(const float4*)&Xs[(ty * 4 + i) * 68 + k4 * 4];
            #pragma unroll
            for (int j = 0; j < 4; j++) {
                float4 w = __ldg(&Wv[(k4 * 4 + j) * 16 + tx]);
                u64 w01 = pk2(w.x, w.y);
                u64 w23 = pk2(w.z, w.w);
                #pragma unroll
                for (int i = 0; i < 4; i++) {
                    float xs = (j == 0) ? xv[i].x : (j == 1) ? xv[i].y : (j == 2) ? xv[i].z : xv[i].w;
                    u64 xd = pk2(xs, xs);
                    fma2(t01[i], xd, w01);
                    fma2(t23[i], xd, w23);
                }
            }
        }
        float4 b = __ldg(&((const float4*)bias)[tx]);
        __syncthreads();               // done reading old Xs
        #pragma unroll
        for (int i = 0; i < 4; i++) {
            int gr = r0 + ty * 4 + i;
            float s = 1.0f;
            if (use_dis) s = (gr < n) ? g_dis[gr] : 0.f;
            float4 a;
            unpk2(t01[i], a.x, a.y);
            unpk2(t23[i], a.z, a.w);
            a.x = fmaxf(fmaf(s, a.x, b.x), 0.f);
            a.y = fmaxf(fmaf(s, a.y, b.y), 0.f);
            a.z = fmaxf(fmaf(s, a.z, b.z), 0.f);
            a.w = fmaxf(fmaf(s, a.w, b.w), 0.f);
            *(float4*)&Xs[(ty * 4 + i) * 68 + tx * 4] = a;
        }
    };

    auto cls_accum = [&](int c) {
        if (tx < 10) {
            #pragma unroll
            for (int k4 = 0; k4 < 16; k4++) {
                float4 xv[4];
                #pragma unroll
                for (int i = 0; i < 4; i++)
                    xv[i] = *(const float4*)&Xs[(ty * 4 + i) * 68 + k4 * 4];
                #pragma unroll
                for (int j = 0; j < 4; j++) {
                    float4 w = Wcs[(c * 64 + k4 * 4 + j) * 10 + tx];
                    u64 w01 = pk2(w.x, w.y);
                    u64 w23 = pk2(w.z, w.w);
                    #pragma unroll
                    for (int i = 0; i < 4; i++) {
                        float xs = (j == 0) ? xv[i].x : (j == 1) ? xv[i].y : (j == 2) ? xv[i].z : xv[i].w;
                        u64 xd = pk2(xs, xs);
                        fma2(c01[i], xd, w01);
                        fma2(c23[i], xd, w23);
                    }
                }
            }
        }
    };

    // phase 0: ego = relu(x @ Wego + bego)
    load_tile(x);
    __syncthreads();
    transform(Wego, bego, false);
    __syncthreads();
    cls_accum(0);
    __syncthreads();

    // phase 1: h1 (materialized)
    load_tile(h1);
    __syncthreads();
    cls_accum(1);
    __syncthreads();

    // phase 2: h2 = relu(dis*(y2 @ Wc1) + b1)
    load_tile(y2);
    __syncthreads();
    transform(Wc1, bc1, true);
    __syncthreads();
    cls_accum(2);

    if (tx < 10) {
        float4 b = ((const float4*)bcls)[tx];
        #pragma unroll
        for (int i = 0; i < 4; i++) {
            int gr = r0 + ty * 4 + i;
            if (gr >= n) continue;
            float4 a;
            unpk2(c01[i], a.x, a.y);
            unpk2(c23[i], a.z, a.w);
            a.x += b.x; a.y += b.y; a.z += b.z; a.w += b.w;
            *(float4*)(out + (size_t)gr * CC + tx * 4) = a;
        }
    }
}

// ---------------- launch -----------------------------------------------------
extern "C" void kernel_launch(void* const* d_in, const int* in_sizes, int n_in,
                              void* d_out, int out_size)
{
    const float* x      = (const float*)d_in[0];
    const void*  ei     = d_in[1];
    const float* W_ego  = (const float*)d_in[2];
    const float* b_ego  = (const float*)d_in[3];
    const float* W_conv = (const float*)d_in[4];   // [2, 64, 64]
    const float* b_conv = (const float*)d_in[5];   // [2, 64]
    const float* W_cls  = (const float*)d_in[6];   // [192, 40]
    const float* b_cls  = (const float*)d_in[7];   // [40]

    const int N = in_sizes[0] / DH;
    const int E = in_sizes[1] / 2;

    float *y, *h1;
    cudaGetSymbolAddress((void**)&y,  g_y);
    cudaGetSymbolAddress((void**)&h1, g_h1);

    const int T = 256;
    const int NB = (N + T - 1) / T;
    const int EB = (E + T - 1) / T;
    const dim3 gb(16, 16);
    const int tile_blocks = (N + 63) / 64;
    const int agg_blocks = (int)(((long long)N * 32 + T - 1) / T);
    const int att_blocks = (int)(((long long)N * ELLW + T - 1) / T);

    // ELL build + normalization + dis attach
    k_init  <<<NB, T>>>(ei, N);
    k_fill  <<<EB, T>>>(ei, E);
    k_dis   <<<NB, T>>>(N);
    k_attach<<<att_blocks, T>>>(N);

    // hop 1
    k_agg   <<<agg_blocks, T>>>(x, y, N);
    k_gemm_h<<<tile_blocks, gb>>>(y, W_conv, b_conv, h1, N);

    // hop 2
    k_agg   <<<agg_blocks, T>>>(h1, y, N);

    // fused classifier
    k_cls<<<tile_blocks, gb>>>(x, h1, y,
                               W_ego, b_ego,
                               W_conv + DH * DH, b_conv + DH,
                               W_cls, b_cls, (float*)d_out, N);
}

// round 15
// speedup vs baseline: 1.1392x; 1.1392x over previous
#include <cuda_runtime.h>
#include <cstdint>

#define MAXN 100000
#define MAXE 1250000
#define DH   64
#define CC   40
#define ELLW 40          // ELL width; Poisson(12.5) => P(deg>40) ~ 1e-10
#define OVFCAP 8192

typedef unsigned long long u64;

// ---- packed f32x2 helpers (sm_10x; PTX-only, ptxas won't auto-fuse) ---------
__device__ __forceinline__ u64 pk2(float lo, float hi) {
    u64 r;
    asm("mov.b64 %0, {%1, %2};" : "=l"(r) : "f"(lo), "f"(hi));
    return r;
}
__device__ __forceinline__ void fma2(u64& d, u64 a, u64 b) {
    asm("fma.rn.f32x2 %0, %1, %2, %0;" : "+l"(d) : "l"(a), "l"(b));
}
__device__ __forceinline__ void unpk2(u64 v, float& lo, float& hi) {
    asm("mov.b64 {%0, %1}, %2;" : "=f"(lo), "=f"(hi) : "l"(v));
}

// ---------------- device scratch (static; no runtime allocation) -------------
__device__ __align__(16) float g_dis[MAXN];
__device__ int   g_deg[MAXN];
__device__ __align__(16) int g_ell[(size_t)MAXN * ELLW];   // 160B rows, aligned
__device__ int2  g_ovf[OVFCAP];
__device__ int   g_ovfn;
__device__ int   g_is64;
__device__ __align__(16) float g_y [(size_t)MAXN * DH];
__device__ __align__(16) float g_h1[(size_t)MAXN * DH];

// ---------------- helpers ----------------------------------------------------
__device__ __forceinline__ int edge_at(const void* ei, long long pos) {
    if (g_is64) return (int)((const long long*)ei)[pos];
    return ((const int*)ei)[pos];
}

// zero deg + overflow counter + int64/int32 detection
__global__ void k_init(const void* ei, int n) {
    int i = blockIdx.x * blockDim.x + threadIdx.x;
    if (i < n) g_deg[i] = 0;
    if (i == 0) {
        g_ovfn = 0;
        const long long* p = (const long long*)ei;
        int ok = 1;
        #pragma unroll
        for (int k = 0; k < 8; k++) {
            long long v = p[k];
            if (v < 0 || v >= (long long)n) ok = 0;
        }
        g_is64 = ok;
    }
}

// single edge pass: deg count + ELL fill (+ overflow capture)
__global__ void k_fill(const void* ei, int E) {
    int e = blockIdx.x * blockDim.x + threadIdx.x;
    if (e < E) {
        int r = edge_at(ei, (long long)e);
        int c = edge_at(ei, (long long)E + e);
        int pos = atomicAdd(&g_deg[c], 1);
        if (pos < ELLW) {
            g_ell[(size_t)c * ELLW + pos] = r;
        } else {
            int k = atomicAdd(&g_ovfn, 1);
            if (k < OVFCAP) g_ovf[k] = make_int2(r, c);
        }
    }
}

__global__ void k_dis(int n) {
    int i = blockIdx.x * blockDim.x + threadIdx.x;
    if (i < n) g_dis[i] = rsqrtf((float)(g_deg[i] + 1));   // +1 = self-loop
}

// -------- gather-first aggregation: y_i = dis_i*src_i + sum_nbr dis_r*src_r ---
// warp per node, lane owns float2; int4-vectorized index loads.
__global__ void k_agg(const float* __restrict__ src, float* __restrict__ y, int n)
{
    int w = (blockIdx.x * blockDim.x + threadIdx.x) >> 5;
    int lane = threadIdx.x & 31;
    if (w >= n) return;

    const float2* Hl = (const float2*)src + lane;   // lane-hoisted base
    float  dw = g_dis[w];
    float2 v0 = Hl[(unsigned)w << 5];
    float2 acc;
    acc.x = dw * v0.x;
    acc.y = dw * v0.y;

    const int deg = g_deg[w];
    const int end = deg < ELLW ? deg : ELLW;
    const int* row = &g_ell[(size_t)w * ELLW];      // 160B rows, 16B-aligned

    int p = 0;
    for (; p + 3 < end; p += 4) {
        int4 v = __ldg((const int4*)(row + p));     // 4 indices, one LDG.128
        float d0 = __ldg(&g_dis[v.x]);
        float d1 = __ldg(&g_dis[v.y]);
        float d2 = __ldg(&g_dis[v.z]);
        float d3 = __ldg(&g_dis[v.w]);
        float2 a = Hl[(unsigned)v.x << 5];
        float2 b = Hl[(unsigned)v.y << 5];
        float2 c = Hl[(unsigned)v.z << 5];
        float2 d = Hl[(unsigned)v.w << 5];
        acc.x = fmaf(d0, a.x, fmaf(d1, b.x, fmaf(d2, c.x, fmaf(d3, d.x, acc.x))));
        acc.y = fmaf(d0, a.y, fmaf(d1, b.y, fmaf(d2, c.y, fmaf(d3, d.y, acc.y))));
    }
    for (; p < end; p++) {
        int s0 = __ldg(&row[p]);
        float d0 = __ldg(&g_dis[s0]);
        float2 a = Hl[(unsigned)s0 << 5];
        acc.x = fmaf(d0, a.x, acc.x);
        acc.y = fmaf(d0, a.y, acc.y);
    }

    // overflow edges (normally none): only overflowing targets scan the buffer
    if (deg > ELLW) {
        int novf = g_ovfn;
        for (int i = 0; i < novf; i++) {
            int2 rc = g_ovf[i];
            if (rc.y == w) {
                float d0 = g_dis[rc.x];
                float2 a = Hl[(unsigned)rc.x << 5];
                acc.x = fmaf(d0, a.x, acc.x);
                acc.y = fmaf(d0, a.y, acc.y);
            }
        }
    }

    ((float2*)y)[((size_t)w << 5) + lane] = acc;
}

// ------------- GEMM+finish: h = relu(dis_i * (y @ W) + b), f32x2 core --------
__global__ void k_gemm_h(const float* __restrict__ Y, const float* __restrict__ W,
                         const float* __restrict__ bias, float* __restrict__ out, int n)
{
    __shared__ float  Xs[64 * 64];
    __shared__ float4 Ws[64 * 16];

    const int tx = threadIdx.x, ty = threadIdx.y;
    const int tid = ty * 16 + tx;

    const float4* Wv = (const float4*)W;
    #pragma unroll
    for (int i = 0; i < 4; i++) Ws[tid + i * 256] = Wv[tid + i * 256];

    const int r0 = blockIdx.x * 64;
    #pragma unroll
    for (int i = 0; i < 4; i++) {
        int idx = tid + i * 256;
        int rr = idx >> 4, cc = idx & 15;
        int gr = r0 + rr;
        float4 v = make_float4(0.f, 0.f, 0.f, 0.f);
        if (gr < n) v = ((const float4*)(Y + (size_t)gr * DH))[cc];
        *(float4*)&Xs[rr * 64 + cc * 4] = v;
    }
    __syncthreads();

    u64 a01[4], a23[4];
    #pragma unroll
    for (int i = 0; i < 4; i++) { a01[i] = 0ull; a23[i] = 0ull; }

    #pragma unroll
    for (int k4 = 0; k4 < 16; k4++) {
        float4 xv[4];
        #pragma unroll
        for (int i = 0; i < 4; i++)
            xv[i] = *(const float4*)&Xs[(ty * 4 + i) * 64 + k4 * 4];
        #pragma unroll
        for (int j = 0; j < 4; j++) {
            float4 w = Ws[(k4 * 4 + j) * 16 + tx];
            u64 w01 = pk2(w.x, w.y);
            u64 w23 = pk2(w.z, w.w);
            #pragma unroll
            for (int i = 0; i < 4; i++) {
                float xs = (j == 0) ? xv[i].x : (j == 1) ? xv[i].y : (j == 2) ? xv[i].z : xv[i].w;
                u64 xd = pk2(xs, xs);
                fma2(a01[i], xd, w01);
                fma2(a23[i], xd, w23);
            }
        }
    }

    float4 b = ((const float4*)bias)[tx];
    #pragma unroll
    for (int i = 0; i < 4; i++) {
        int gr = r0 + ty * 4 + i;
        if (gr >= n) continue;
        float s = g_dis[gr];
        float4 a;
        unpk2(a01[i], a.x, a.y);
        unpk2(a23[i], a.z, a.w);
        a.x = fmaxf(fmaf(s, a.x, b.x), 0.f);
        a.y = fmaxf(fmaf(s, a.y, b.y), 0.f);
        a.z = fmaxf(fmaf(s, a.z, b.z), 0.f);
        a.w = fmaxf(fmaf(s, a.w, b.w), 0.f);
        ((float4*)(out + (size_t)gr * DH))[tx] = a;
    }
}

// ---------------- fused classifier, f32x2 core --------------------------------
__global__ void k_cls(const float* __restrict__ x, const float* __restrict__ h1,
                      const float* __restrict__ y2,
                      const float* __restrict__ Wego, const float* __restrict__ bego,
                      const float* __restrict__ Wc1,  const float* __restrict__ bc1,
                      const float* __restrict__ Wcls, const float* __restrict__ bcls,
                      float* __restrict__ out, int n)
{
    __shared__ float  Xs[64 * 68];     // 17408 B
    __shared__ float4 Wcs[192 * 10];   // 30720 B

    const int tx = threadIdx.x, ty = threadIdx.y;
    const int tid = ty * 16 + tx;
    const int r0 = blockIdx.x * 64;

    const float4* Wclsv = (const float4*)Wcls;
    #pragma unroll
    for (int i = tid; i < 1920; i += 256) Wcs[i] = Wclsv[i];

    u64 c01[4], c23[4];
    #pragma unroll
    for (int i = 0; i < 4; i++) { c01[i] = 0ull; c23[i] = 0ull; }

    auto load_tile = [&](const float* S) {
        #pragma unroll
        for (int i = 0; i < 4; i++) {
            int idx = tid + i * 256;
            int rr = idx >> 4, cc = idx & 15;
            int gr = r0 + rr;
            float4 v = make_float4(0.f, 0.f, 0.f, 0.f);
            if (gr < n) v = ((const float4*)(S + (size_t)gr * DH))[cc];
            *(float4*)&Xs[rr * 68 + cc * 4] = v;
        }
    };

    auto transform = [&](const float* W, const float* bias, bool use_dis) {
        const float4* Wv = (const float4*)W;
        u64 t01[4], t23[4];
        #pragma unroll
        for (int i = 0; i < 4; i++) { t01[i] = 0ull; t23[i] = 0ull; }
        #pragma unroll
        for (int k4 = 0; k4 < 16; k4++) {
            float4 xv[4];
            #pragma unroll
            for (int i = 0; i < 4; i++)
                xv[i] = *(const float4*)&Xs[(ty * 4 + i) * 68 + k4 * 4];
            #pragma unroll
            for (int j = 0; j < 4; j++) {
                float4 w = __ldg(&Wv[(k4 * 4 + j) * 16 + tx]);
                u64 w01 = pk2(w.x, w.y);
                u64 w23 = pk2(w.z, w.w);
                #pragma unroll
                for (int i = 0; i < 4; i++) {
                    float xs = (j == 0) ? xv[i].x : (j == 1) ? xv[i].y : (j == 2) ? xv[i].z : xv[i].w;
                    u64 xd = pk2(xs, xs);
                    fma2(t01[i], xd, w01);
                    fma2(t23[i], xd, w23);
                }
            }
        }
        float4 b = __ldg(&((const float4*)bias)[tx]);
        __syncthreads();               // done reading old Xs
        #pragma unroll
        for (int i = 0; i < 4; i++) {
            int gr = r0 + ty * 4 + i;
            float s = 1.0f;
            if (use_dis) s = (gr < n) ? g_dis[gr] : 0.f;
            float4 a;
            unpk2(t01[i], a.x, a.y);
            unpk2(t23[i], a.z, a.w);
            a.x = fmaxf(fmaf(s, a.x, b.x), 0.f);
            a.y = fmaxf(fmaf(s, a.y, b.y), 0.f);
            a.z = fmaxf(fmaf(s, a.z, b.z), 0.f);
            a.w = fmaxf(fmaf(s, a.w, b.w), 0.f);
            *(float4*)&Xs[(ty * 4 + i) * 68 + tx * 4] = a;
        }
    };

    auto cls_accum = [&](int c) {
        if (tx < 10) {
            #pragma unroll
            for (int k4 = 0; k4 < 16; k4++) {
                float4 xv[4];
                #pragma unroll
                for (int i = 0; i < 4; i++)
                    xv[i] = *(const float4*)&Xs[(ty * 4 + i) * 68 + k4 * 4];
                #pragma unroll
                for (int j = 0; j < 4; j++) {
                    float4 w = Wcs[(c * 64 + k4 * 4 + j) * 10 + tx];
                    u64 w01 = pk2(w.x, w.y);
                    u64 w23 = pk2(w.z, w.w);
                    #pragma unroll
                    for (int i = 0; i < 4; i++) {
                        float xs = (j == 0) ? xv[i].x : (j == 1) ? xv[i].y : (j == 2) ? xv[i].z : xv[i].w;
                        u64 xd = pk2(xs, xs);
                        fma2(c01[i], xd, w01);
                        fma2(c23[i], xd, w23);
                    }
                }
            }
        }
    };

    // phase 0: ego = relu(x @ Wego + bego)
    load_tile(x);
    __syncthreads();
    transform(Wego, bego, false);
    __syncthreads();
    cls_accum(0);
    __syncthreads();

    // phase 1: h1 (materialized)
    load_tile(h1);
    __syncthreads();
    cls_accum(1);
    __syncthreads();

    // phase 2: h2 = relu(dis*(y2 @ Wc1) + b1)
    load_tile(y2);
    __syncthreads();
    transform(Wc1, bc1, true);
    __syncthreads();
    cls_accum(2);

    if (tx < 10) {
        float4 b = ((const float4*)bcls)[tx];
        #pragma unroll
        for (int i = 0; i < 4; i++) {
            int gr = r0 + ty * 4 + i;
            if (gr >= n) continue;
            float4 a;
            unpk2(c01[i], a.x, a.y);
            unpk2(c23[i], a.z, a.w);
            a.x += b.x; a.y += b.y; a.z += b.z; a.w += b.w;
            *(float4*)(out + (size_t)gr * CC + tx * 4) = a;
        }
    }
}

// ---------------- launch -----------------------------------------------------
extern "C" void kernel_launch(void* const* d_in, const int* in_sizes, int n_in,
                              void* d_out, int out_size)
{
    const float* x      = (const float*)d_in[0];
    const void*  ei     = d_in[1];
    const float* W_ego  = (const float*)d_in[2];
    const float* b_ego  = (const float*)d_in[3];
    const float* W_conv = (const float*)d_in[4];   // [2, 64, 64]
    const float* b_conv = (const float*)d_in[5];   // [2, 64]
    const float* W_cls  = (const float*)d_in[6];   // [192, 40]
    const float* b_cls  = (const float*)d_in[7];   // [40]

    const int N = in_sizes[0] / DH;
    const int E = in_sizes[1] / 2;

    float *y, *h1;
    cudaGetSymbolAddress((void**)&y,  g_y);
    cudaGetSymbolAddress((void**)&h1, g_h1);

    const int T = 256;
    const int NB = (N + T - 1) / T;
    const int EB = (E + T - 1) / T;
    const dim3 gb(16, 16);
    const int tile_blocks = (N + 63) / 64;
    const int agg_blocks = (int)(((long long)N * 32 + T - 1) / T);

    // ELL build + normalization
    k_init<<<NB, T>>>(ei, N);
    k_fill<<<EB, T>>>(ei, E);
    k_dis <<<NB, T>>>(N);

    // hop 1
    k_agg   <<<agg_blocks, T>>>(x, y, N);
    k_gemm_h<<<tile_blocks, gb>>>(y, W_conv, b_conv, h1, N);

    // hop 2
    k_agg   <<<agg_blocks, T>>>(h1, y, N);

    // fused classifier
    k_cls<<<tile_blocks, gb>>>(x, h1, y,
                               W_ego, b_ego,
                               W_conv + DH * DH, b_conv + DH,
                               W_cls, b_cls, (float*)d_out, N);
}

// round 16
// speedup vs baseline: 1.1453x; 1.0053x over previous
#include <cuda_runtime.h>
#include <cstdint>

#define MAXN 100000
#define MAXE 1250000
#define DH   64
#define CC   40
#define ELLW 40          // ELL width; Poisson(12.5) => P(deg>40) ~ 1e-10
#define OVFCAP 8192

typedef unsigned long long u64;

// ---- packed f32x2 helpers (sm_10x; PTX-only, ptxas won't auto-fuse) ---------
__device__ __forceinline__ u64 pk2(float lo, float hi) {
    u64 r;
    asm("mov.b64 %0, {%1, %2};" : "=l"(r) : "f"(lo), "f"(hi));
    return r;
}
__device__ __forceinline__ void fma2(u64& d, u64 a, u64 b) {
    asm("fma.rn.f32x2 %0, %1, %2, %0;" : "+l"(d) : "l"(a), "l"(b));
}
__device__ __forceinline__ void unpk2(u64 v, float& lo, float& hi) {
    asm("mov.b64 {%0, %1}, %2;" : "=f"(lo), "=f"(hi) : "l"(v));
}

// ---------------- device scratch (static; no runtime allocation) -------------
__device__ __align__(16) float g_dis[MAXN];
__device__ int   g_deg[MAXN];
__device__ __align__(16) int g_ell[(size_t)MAXN * ELLW];   // 160B rows, aligned
__device__ int2  g_ovf[OVFCAP];
__device__ int   g_ovfn;
__device__ int   g_is64;
__device__ __align__(16) float g_z [(size_t)MAXN * DH];    // dis-prescaled source
__device__ __align__(16) float g_y [(size_t)MAXN * DH];
__device__ __align__(16) float g_h1[(size_t)MAXN * DH];

// ---------------- helpers ----------------------------------------------------
__device__ __forceinline__ int edge_at(const void* ei, long long pos) {
    if (g_is64) return (int)((const long long*)ei)[pos];
    return ((const int*)ei)[pos];
}

// zero deg + overflow counter + int64/int32 detection
__global__ void k_init(const void* ei, int n) {
    int i = blockIdx.x * blockDim.x + threadIdx.x;
    if (i < n) g_deg[i] = 0;
    if (i == 0) {
        g_ovfn = 0;
        const long long* p = (const long long*)ei;
        int ok = 1;
        #pragma unroll
        for (int k = 0; k < 8; k++) {
            long long v = p[k];
            if (v < 0 || v >= (long long)n) ok = 0;
        }
        g_is64 = ok;
    }
}

// single edge pass: deg count + ELL fill (+ overflow capture)
__global__ void k_fill(const void* ei, int E) {
    int e = blockIdx.x * blockDim.x + threadIdx.x;
    if (e < E) {
        int r = edge_at(ei, (long long)e);
        int c = edge_at(ei, (long long)E + e);
        int pos = atomicAdd(&g_deg[c], 1);
        if (pos < ELLW) {
            g_ell[(size_t)c * ELLW + pos] = r;
        } else {
            int k = atomicAdd(&g_ovfn, 1);
            if (k < OVFCAP) g_ovf[k] = make_int2(r, c);
        }
    }
}

__global__ void k_dis(int n) {
    int i = blockIdx.x * blockDim.x + threadIdx.x;
    if (i < n) g_dis[i] = rsqrtf((float)(g_deg[i] + 1));   // +1 = self-loop
}

// z[i] = dis[node] * x[i]  (dense row scale, float4 lanes)
__global__ void k_prescale(const float* __restrict__ x, int n) {
    int i = blockIdx.x * blockDim.x + threadIdx.x;         // over n*16 float4
    if (i >= n * 16) return;
    int node = i >> 4;
    float d = g_dis[node];
    float4 v = ((const float4*)x)[i];
    v.x *= d; v.y *= d; v.z *= d; v.w *= d;
    ((float4*)g_z)[i] = v;
}

// -------- aggregation on prescaled source: y_i = z_i + sum_nbr z_r -----------
// warp per node, lane owns float2; int4 index loads; NO per-edge dis loads.
__global__ void k_agg(const float* __restrict__ z, float* __restrict__ y, int n)
{
    int w = (blockIdx.x * blockDim.x + threadIdx.x) >> 5;
    int lane = threadIdx.x & 31;
    if (w >= n) return;

    const float2* Zl = (const float2*)z + lane;     // lane-hoisted base
    float2 acc = Zl[(unsigned)w << 5];              // self term (pre-scaled)

    const int deg = g_deg[w];
    const int end = deg < ELLW ? deg : ELLW;
    const int* row = &g_ell[(size_t)w * ELLW];      // 160B rows, 16B-aligned

    int p = 0;
    for (; p + 3 < end; p += 4) {
        int4 v = __ldg((const int4*)(row + p));     // 4 indices, one LDG.128
        float2 a = Zl[(unsigned)v.x << 5];
        float2 b = Zl[(unsigned)v.y << 5];
        float2 c = Zl[(unsigned)v.z << 5];
        float2 d = Zl[(unsigned)v.w << 5];
        acc.x += (a.x + b.x) + (c.x + d.x);
        acc.y += (a.y + b.y) + (c.y + d.y);
    }
    for (; p < end; p++) {
        int s0 = __ldg(&row[p]);
        float2 a = Zl[(unsigned)s0 << 5];
        acc.x += a.x;
        acc.y += a.y;
    }

    // overflow edges (normally none): only overflowing targets scan the buffer
    if (deg > ELLW) {
        int novf = g_ovfn;
        for (int i = 0; i < novf; i++) {
            int2 rc = g_ovf[i];
            if (rc.y == w) {
                float2 a = Zl[(unsigned)rc.x << 5];
                acc.x += a.x;
                acc.y += a.y;
            }
        }
    }

    ((float2*)y)[((size_t)w << 5) + lane] = acc;
}

// --- GEMM+finish: h1 = relu(dis*(y@W)+b); also z = dis*h1 (for hop-2 agg) ----
__global__ void k_gemm_h(const float* __restrict__ Y, const float* __restrict__ W,
                         const float* __restrict__ bias, float* __restrict__ out, int n)
{
    __shared__ float  Xs[64 * 64];
    __shared__ float4 Ws[64 * 16];

    const int tx = threadIdx.x, ty = threadIdx.y;
    const int tid = ty * 16 + tx;

    const float4* Wv = (const float4*)W;
    #pragma unroll
    for (int i = 0; i < 4; i++) Ws[tid + i * 256] = Wv[tid + i * 256];

    const int r0 = blockIdx.x * 64;
    #pragma unroll
    for (int i = 0; i < 4; i++) {
        int idx = tid + i * 256;
        int rr = idx >> 4, cc = idx & 15;
        int gr = r0 + rr;
        float4 v = make_float4(0.f, 0.f, 0.f, 0.f);
        if (gr < n) v = ((const float4*)(Y + (size_t)gr * DH))[cc];
        *(float4*)&Xs[rr * 64 + cc * 4] = v;
    }
    __syncthreads();

    u64 a01[4], a23[4];
    #pragma unroll
    for (int i = 0; i < 4; i++) { a01[i] = 0ull; a23[i] = 0ull; }

    #pragma unroll
    for (int k4 = 0; k4 < 16; k4++) {
        float4 xv[4];
        #pragma unroll
        for (int i = 0; i < 4; i++)
            xv[i] = *(const float4*)&Xs[(ty * 4 + i) * 64 + k4 * 4];
        #pragma unroll
        for (int j = 0; j < 4; j++) {
            float4 w = Ws[(k4 * 4 + j) * 16 + tx];
            u64 w01 = pk2(w.x, w.y);
            u64 w23 = pk2(w.z, w.w);
            #pragma unroll
            for (int i = 0; i < 4; i++) {
                float xs = (j == 0) ? xv[i].x : (j == 1) ? xv[i].y : (j == 2) ? xv[i].z : xv[i].w;
                u64 xd = pk2(xs, xs);
                fma2(a01[i], xd, w01);
                fma2(a23[i], xd, w23);
            }
        }
    }

    float4 b = ((const float4*)bias)[tx];
    #pragma unroll
    for (int i = 0; i < 4; i++) {
        int gr = r0 + ty * 4 + i;
        if (gr >= n) continue;
        float s = g_dis[gr];
        float4 a;
        unpk2(a01[i], a.x, a.y);
        unpk2(a23[i], a.z, a.w);
        a.x = fmaxf(fmaf(s, a.x, b.x), 0.f);
        a.y = fmaxf(fmaf(s, a.y, b.y), 0.f);
        a.z = fmaxf(fmaf(s, a.z, b.z), 0.f);
        a.w = fmaxf(fmaf(s, a.w, b.w), 0.f);
        ((float4*)(out + (size_t)gr * DH))[tx] = a;
        // prescaled copy for hop-2 aggregation: z = dis * h1
        float4 zc = make_float4(s * a.x, s * a.y, s * a.z, s * a.w);
        ((float4*)(g_z + (size_t)gr * DH))[tx] = zc;
    }
}

// ---------------- fused classifier, f32x2 core --------------------------------
__global__ void k_cls(const float* __restrict__ x, const float* __restrict__ h1,
                      const float* __restrict__ y2,
                      const float* __restrict__ Wego, const float* __restrict__ bego,
                      const float* __restrict__ Wc1,  const float* __restrict__ bc1,
                      const float* __restrict__ Wcls, const float* __restrict__ bcls,
                      float* __restrict__ out, int n)
{
    __shared__ float  Xs[64 * 68];     // 17408 B
    __shared__ float4 Wcs[192 * 10];   // 30720 B

    const int tx = threadIdx.x, ty = threadIdx.y;
    const int tid = ty * 16 + tx;
    const int r0 = blockIdx.x * 64;

    const float4* Wclsv = (const float4*)Wcls;
    #pragma unroll
    for (int i = tid; i < 1920; i += 256) Wcs[i] = Wclsv[i];

    u64 c01[4], c23[4];
    #pragma unroll
    for (int i = 0; i < 4; i++) { c01[i] = 0ull; c23[i] = 0ull; }

    auto load_tile = [&](const float* S) {
        #pragma unroll
        for (int i = 0; i < 4; i++) {
            int idx = tid + i * 256;
            int rr = idx >> 4, cc = idx & 15;
            int gr = r0 + rr;
            float4 v = make_float4(0.f, 0.f, 0.f, 0.f);
            if (gr < n) v = ((const float4*)(S + (size_t)gr * DH))[cc];
            *(float4*)&Xs[rr * 68 + cc * 4] = v;
        }
    };

    auto transform = [&](const float* W, const float* bias, bool use_dis) {
        const float4* Wv = (const float4*)W;
        u64 t01[4], t23[4];
        #pragma unroll
        for (int i = 0; i < 4; i++) { t01[i] = 0ull; t23[i] = 0ull; }
        #pragma unroll
        for (int k4 = 0; k4 < 16; k4++) {
            float4 xv[4];
            #pragma unroll
            for (int i = 0; i < 4; i++)
                xv[i] = *(const float4*)&Xs[(ty * 4 + i) * 68 + k4 * 4];
            #pragma unroll
            for (int j = 0; j < 4; j++) {
                float4 w = __ldg(&Wv[(k4 * 4 + j) * 16 + tx]);
                u64 w01 = pk2(w.x, w.y);
                u64 w23 = pk2(w.z, w.w);
                #pragma unroll
                for (int i = 0; i < 4; i++) {
                    float xs = (j == 0) ? xv[i].x : (j == 1) ? xv[i].y : (j == 2) ? xv[i].z : xv[i].w;
                    u64 xd = pk2(xs, xs);
                    fma2(t01[i], xd, w01);
                    fma2(t23[i], xd, w23);
                }
            }
        }
        float4 b = __ldg(&((const float4*)bias)[tx]);
        __syncthreads();               // done reading old Xs
        #pragma unroll
        for (int i = 0; i < 4; i++) {
            int gr = r0 + ty * 4 + i;
            float s = 1.0f;
            if (use_dis) s = (gr < n) ? g_dis[gr] : 0.f;
            float4 a;
            unpk2(t01[i], a.x, a.y);
            unpk2(t23[i], a.z, a.w);
            a.x = fmaxf(fmaf(s, a.x, b.x), 0.f);
            a.y = fmaxf(fmaf(s, a.y, b.y), 0.f);
            a.z = fmaxf(fmaf(s, a.z, b.z), 0.f);
            a.w = fmaxf(fmaf(s, a.w, b.w), 0.f);
            *(float4*)&Xs[(ty * 4 + i) * 68 + tx * 4] = a;
        }
    };

    auto cls_accum = [&](int c) {
        if (tx < 10) {
            #pragma unroll
            for (int k4 = 0; k4 < 16; k4++) {
                float4 xv[4];
                #pragma unroll
                for (int i = 0; i < 4; i++)
                    xv[i] = *(const float4*)&Xs[(ty * 4 + i) * 68 + k4 * 4];
                #pragma unroll
                for (int j = 0; j < 4; j++) {
                    float4 w = Wcs[(c * 64 + k4 * 4 + j) * 10 + tx];
                    u64 w01 = pk2(w.x, w.y);
                    u64 w23 = pk2(w.z, w.w);
                    #pragma unroll
                    for (int i = 0; i < 4; i++) {
                        float xs = (j == 0) ? xv[i].x : (j == 1) ? xv[i].y : (j == 2) ? xv[i].z : xv[i].w;
                        u64 xd = pk2(xs, xs);
                        fma2(c01[i], xd, w01);
                        fma2(c23[i], xd, w23);
                    }
                }
            }
        }
    };

    // phase 0: ego = relu(x @ Wego + bego)
    load_tile(x);
    __syncthreads();
    transform(Wego, bego, false);
    __syncthreads();
    cls_accum(0);
    __syncthreads();

    // phase 1: h1 (materialized)
    load_tile(h1);
    __syncthreads();
    cls_accum(1);
    __syncthreads();

    // phase 2: h2 = relu(dis*(y2 @ Wc1) + b1)
    load_tile(y2);
    __syncthreads();
    transform(Wc1, bc1, true);
    __syncthreads();
    cls_accum(2);

    if (tx < 10) {
        float4 b = ((const float4*)bcls)[tx];
        #pragma unroll
        for (int i = 0; i < 4; i++) {
            int gr = r0 + ty * 4 + i;
            if (gr >= n) continue;
            float4 a;
            unpk2(c01[i], a.x, a.y);
            unpk2(c23[i], a.z, a.w);
            a.x += b.x; a.y += b.y; a.z += b.z; a.w += b.w;
            *(float4*)(out + (size_t)gr * CC + tx * 4) = a;
        }
    }
}

// ---------------- launch -----------------------------------------------------
extern "C" void kernel_launch(void* const* d_in, const int* in_sizes, int n_in,
                              void* d_out, int out_size)
{
    const float* x      = (const float*)d_in[0];
    const void*  ei     = d_in[1];
    const float* W_ego  = (const float*)d_in[2];
    const float* b_ego  = (const float*)d_in[3];
    const float* W_conv = (const float*)d_in[4];   // [2, 64, 64]
    const float* b_conv = (const float*)d_in[5];   // [2, 64]
    const float* W_cls  = (const float*)d_in[6];   // [192, 40]
    const float* b_cls  = (const float*)d_in[7];   // [40]

    const int N = in_sizes[0] / DH;
    const int E = in_sizes[1] / 2;

    float *y, *h1, *z;
    cudaGetSymbolAddress((void**)&y,  g_y);
    cudaGetSymbolAddress((void**)&h1, g_h1);
    cudaGetSymbolAddress((void**)&z,  g_z);

    const int T = 256;
    const int NB = (N + T - 1) / T;
    const int EB = (E + T - 1) / T;
    const dim3 gb(16, 16);
    const int tile_blocks = (N + 63) / 64;
    const int agg_blocks = (int)(((long long)N * 32 + T - 1) / T);
    const int pre_blocks = (int)(((long long)N * 16 + T - 1) / T);

    // ELL build + normalization + x prescale
    k_init    <<<NB, T>>>(ei, N);
    k_fill    <<<EB, T>>>(ei, E);
    k_dis     <<<NB, T>>>(N);
    k_prescale<<<pre_blocks, T>>>(x, N);

    // hop 1: y1 = z_self + gather(z);  h1 = relu(dis*(y1@Wc0)+b0); z = dis*h1
    k_agg   <<<agg_blocks, T>>>(z, y, N);
    k_gemm_h<<<tile_blocks, gb>>>(y, W_conv, b_conv, h1, N);

    // hop 2: y2 = z_self + gather(z)
    k_agg   <<<agg_blocks, T>>>(z, y, N);

    // fused classifier
    k_cls<<<tile_blocks, gb>>>(x, h1, y,
                               W_ego, b_ego,
                               W_conv + DH * DH, b_conv + DH,
                               W_cls, b_cls, (float*)d_out, N);
}

// round 17
// speedup vs baseline: 1.1746x; 1.0256x over previous
#include <cuda_runtime.h>
#include <cstdint>

#define MAXN 100000
#define MAXE 1250000
#define DH   64
#define CC   40
#define ELLW 40          // ELL width; Poisson(12.5) => P(deg>40) ~ 1e-10
#define OVFCAP 8192

typedef unsigned long long u64;

// ---- packed f32x2 helpers (sm_10x; PTX-only, ptxas won't auto-fuse) ---------
__device__ __forceinline__ u64 pk2(float lo, float hi) {
    u64 r;
    asm("mov.b64 %0, {%1, %2};" : "=l"(r) : "f"(lo), "f"(hi));
    return r;
}
__device__ __forceinline__ void fma2(u64& d, u64 a, u64 b) {
    asm("fma.rn.f32x2 %0, %1, %2, %0;" : "+l"(d) : "l"(a), "l"(b));
}
__device__ __forceinline__ void unpk2(u64 v, float& lo, float& hi) {
    asm("mov.b64 {%0, %1}, %2;" : "=f"(lo), "=f"(hi) : "l"(v));
}

// ---------------- device scratch (static; no runtime allocation) -------------
__device__ __align__(16) float g_dis[MAXN];
__device__ int   g_deg[MAXN];
__device__ __align__(16) int g_ell[(size_t)MAXN * ELLW];   // 160B rows, aligned
__device__ int2  g_ovf[OVFCAP];
__device__ int   g_ovfn;
__device__ int   g_is64;
__device__ __align__(16) float g_z [(size_t)MAXN * DH];    // dis-prescaled source
__device__ __align__(16) float g_y [(size_t)MAXN * DH];
__device__ __align__(16) float g_h1[(size_t)MAXN * DH];

// ---------------- helpers ----------------------------------------------------
__device__ __forceinline__ int edge_at(const void* ei, long long pos) {
    if (g_is64) return (int)((const long long*)ei)[pos];
    return ((const int*)ei)[pos];
}

// zero deg + overflow counter + int64/int32 detection
__global__ void k_init(const void* ei, int n) {
    int i = blockIdx.x * blockDim.x + threadIdx.x;
    if (i < n) g_deg[i] = 0;
    if (i == 0) {
        g_ovfn = 0;
        const long long* p = (const long long*)ei;
        int ok = 1;
        #pragma unroll
        for (int k = 0; k < 8; k++) {
            long long v = p[k];
            if (v < 0 || v >= (long long)n) ok = 0;
        }
        g_is64 = ok;
    }
}

// edge pass, 2 edges/thread: deg count + ELL fill (+ overflow capture)
__global__ void k_fill(const void* ei, int E) {
    int t = blockIdx.x * blockDim.x + threadIdx.x;
    int e0 = t * 2;
    if (e0 >= E) return;

    int r0, c0, r1 = 0, c1 = 0;
    const bool two = (e0 + 1 < E);
    if (g_is64) {
        const long long* p = (const long long*)ei;
        longlong2 rr = *(const longlong2*)(p + e0);          // 16B-aligned (e0 even)
        longlong2 cc = *(const longlong2*)(p + E + e0);      // E even => aligned
        r0 = (int)rr.x; r1 = (int)rr.y;
        c0 = (int)cc.x; c1 = (int)cc.y;
    } else {
        const int* p = (const int*)ei;
        int2 rr = *(const int2*)(p + e0);
        int2 cc = *(const int2*)(p + E + e0);
        r0 = rr.x; r1 = rr.y;
        c0 = cc.x; c1 = cc.y;
    }

    int pos0 = atomicAdd(&g_deg[c0], 1);
    if (pos0 < ELLW) g_ell[(size_t)c0 * ELLW + pos0] = r0;
    else {
        int k = atomicAdd(&g_ovfn, 1);
        if (k < OVFCAP) g_ovf[k] = make_int2(r0, c0);
    }
    if (two) {
        int pos1 = atomicAdd(&g_deg[c1], 1);
        if (pos1 < ELLW) g_ell[(size_t)c1 * ELLW + pos1] = r1;
        else {
            int k = atomicAdd(&g_ovfn, 1);
            if (k < OVFCAP) g_ovf[k] = make_int2(r1, c1);
        }
    }
}

// dis computation + z = dis*x, fused (16 threads per node)
__global__ void k_disprescale(const float* __restrict__ x, int n) {
    int i = blockIdx.x * blockDim.x + threadIdx.x;         // over n*16 float4
    if (i >= n * 16) return;
    int node = i >> 4;
    float d = rsqrtf((float)(g_deg[node] + 1));            // +1 = self-loop
    if ((i & 15) == 0) g_dis[node] = d;
    float4 v = ((const float4*)x)[i];
    v.x *= d; v.y *= d; v.z *= d; v.w *= d;
    ((float4*)g_z)[i] = v;
}

// -------- aggregation on prescaled source: y_i = z_i + sum_nbr z_r -----------
// warp per node, lane owns float2; int4 index loads; unroll-8 for MLP.
__global__ void k_agg(const float* __restrict__ z, float* __restrict__ y, int n)
{
    int w = (blockIdx.x * blockDim.x + threadIdx.x) >> 5;
    int lane = threadIdx.x & 31;
    if (w >= n) return;

    const float2* Zl = (const float2*)z + lane;     // lane-hoisted base
    float2 acc = Zl[(unsigned)w << 5];              // self term (pre-scaled)

    const int deg = g_deg[w];
    const int end = deg < ELLW ? deg : ELLW;
    const int* row = &g_ell[(size_t)w * ELLW];      // 160B rows, 16B-aligned

    int p = 0;
    for (; p + 7 < end; p += 8) {
        int4 v0 = __ldg((const int4*)(row + p));
        int4 v1 = __ldg((const int4*)(row + p + 4));
        float2 a = Zl[(unsigned)v0.x << 5];
        float2 b = Zl[(unsigned)v0.y << 5];
        float2 c = Zl[(unsigned)v0.z << 5];
        float2 d = Zl[(unsigned)v0.w << 5];
        float2 e = Zl[(unsigned)v1.x << 5];
        float2 f = Zl[(unsigned)v1.y << 5];
        float2 g = Zl[(unsigned)v1.z << 5];
        float2 h = Zl[(unsigned)v1.w << 5];
        acc.x += ((a.x + b.x) + (c.x + d.x)) + ((e.x + f.x) + (g.x + h.x));
        acc.y += ((a.y + b.y) + (c.y + d.y)) + ((e.y + f.y) + (g.y + h.y));
    }
    for (; p + 3 < end; p += 4) {
        int4 v = __ldg((const int4*)(row + p));
        float2 a = Zl[(unsigned)v.x << 5];
        float2 b = Zl[(unsigned)v.y << 5];
        float2 c = Zl[(unsigned)v.z << 5];
        float2 d = Zl[(unsigned)v.w << 5];
        acc.x += (a.x + b.x) + (c.x + d.x);
        acc.y += (a.y + b.y) + (c.y + d.y);
    }
    for (; p < end; p++) {
        int s0 = __ldg(&row[p]);
        float2 a = Zl[(unsigned)s0 << 5];
        acc.x += a.x;
        acc.y += a.y;
    }

    // overflow edges (normally none): only overflowing targets scan the buffer
    if (deg > ELLW) {
        int novf = g_ovfn;
        for (int i = 0; i < novf; i++) {
            int2 rc = g_ovf[i];
            if (rc.y == w) {
                float2 a = Zl[(unsigned)rc.x << 5];
                acc.x += a.x;
                acc.y += a.y;
            }
        }
    }

    ((float2*)y)[((size_t)w << 5) + lane] = acc;
}

// --- GEMM+finish: h1 = relu(dis*(y@W)+b); also z = dis*h1 (for hop-2 agg) ----
__global__ void k_gemm_h(const float* __restrict__ Y, const float* __restrict__ W,
                         const float* __restrict__ bias, float* __restrict__ out, int n)
{
    __shared__ float  Xs[64 * 64];
    __shared__ float4 Ws[64 * 16];

    const int tx = threadIdx.x, ty = threadIdx.y;
    const int tid = ty * 16 + tx;

    const float4* Wv = (const float4*)W;
    #pragma unroll
    for (int i = 0; i < 4; i++) Ws[tid + i * 256] = Wv[tid + i * 256];

    const int r0 = blockIdx.x * 64;
    #pragma unroll
    for (int i = 0; i < 4; i++) {
        int idx = tid + i * 256;
        int rr = idx >> 4, cc = idx & 15;
        int gr = r0 + rr;
        float4 v = make_float4(0.f, 0.f, 0.f, 0.f);
        if (gr < n) v = ((const float4*)(Y + (size_t)gr * DH))[cc];
        *(float4*)&Xs[rr * 64 + cc * 4] = v;
    }
    __syncthreads();

    u64 a01[4], a23[4];
    #pragma unroll
    for (int i = 0; i < 4; i++) { a01[i] = 0ull; a23[i] = 0ull; }

    #pragma unroll
    for (int k4 = 0; k4 < 16; k4++) {
        float4 xv[4];
        #pragma unroll
        for (int i = 0; i < 4; i++)
            xv[i] = *(const float4*)&Xs[(ty * 4 + i) * 64 + k4 * 4];
        #pragma unroll
        for (int j = 0; j < 4; j++) {
            float4 w = Ws[(k4 * 4 + j) * 16 + tx];
            u64 w01 = pk2(w.x, w.y);
            u64 w23 = pk2(w.z, w.w);
            #pragma unroll
            for (int i = 0; i < 4; i++) {
                float xs = (j == 0) ? xv[i].x : (j == 1) ? xv[i].y : (j == 2) ? xv[i].z : xv[i].w;
                u64 xd = pk2(xs, xs);
                fma2(a01[i], xd, w01);
                fma2(a23[i], xd, w23);
            }
        }
    }

    float4 b = ((const float4*)bias)[tx];
    #pragma unroll
    for (int i = 0; i < 4; i++) {
        int gr = r0 + ty * 4 + i;
        if (gr >= n) continue;
        float s = g_dis[gr];
        float4 a;
        unpk2(a01[i], a.x, a.y);
        unpk2(a23[i], a.z, a.w);
        a.x = fmaxf(fmaf(s, a.x, b.x), 0.f);
        a.y = fmaxf(fmaf(s, a.y, b.y), 0.f);
        a.z = fmaxf(fmaf(s, a.z, b.z), 0.f);
        a.w = fmaxf(fmaf(s, a.w, b.w), 0.f);
        ((float4*)(out + (size_t)gr * DH))[tx] = a;
        // prescaled copy for hop-2 aggregation: z = dis * h1
        float4 zc = make_float4(s * a.x, s * a.y, s * a.z, s * a.w);
        ((float4*)(g_z + (size_t)gr * DH))[tx] = zc;
    }
}

// ---------------- fused classifier, f32x2 core --------------------------------
__global__ void k_cls(const float* __restrict__ x, const float* __restrict__ h1,
                      const float* __restrict__ y2,
                      const float* __restrict__ Wego, const float* __restrict__ bego,
                      const float* __restrict__ Wc1,  const float* __restrict__ bc1,
                      const float* __restrict__ Wcls, const float* __restrict__ bcls,
                      float* __restrict__ out, int n)
{
    __shared__ float  Xs[64 * 68];     // 17408 B
    __shared__ float4 Wcs[192 * 10];   // 30720 B

    const int tx = threadIdx.x, ty = threadIdx.y;
    const int tid = ty * 16 + tx;
    const int r0 = blockIdx.x * 64;

    const float4* Wclsv = (const float4*)Wcls;
    #pragma unroll
    for (int i = tid; i < 1920; i += 256) Wcs[i] = Wclsv[i];

    u64 c01[4], c23[4];
    #pragma unroll
    for (int i = 0; i < 4; i++) { c01[i] = 0ull; c23[i] = 0ull; }

    auto load_tile = [&](const float* S) {
        #pragma unroll
        for (int i = 0; i < 4; i++) {
            int idx = tid + i * 256;
            int rr = idx >> 4, cc = idx & 15;
            int gr = r0 + rr;
            float4 v = make_float4(0.f, 0.f, 0.f, 0.f);
            if (gr < n) v = ((const float4*)(S + (size_t)gr * DH))[cc];
            *(float4*)&Xs[rr * 68 + cc * 4] = v;
        }
    };

    auto transform = [&](const float* W, const float* bias, bool use_dis) {
        const float4* Wv = (const float4*)W;
        u64 t01[4], t23[4];
        #pragma unroll
        for (int i = 0; i < 4; i++) { t01[i] = 0ull; t23[i] = 0ull; }
        #pragma unroll
        for (int k4 = 0; k4 < 16; k4++) {
            float4 xv[4];
            #pragma unroll
            for (int i = 0; i < 4; i++)
                xv[i] = *(const float4*)&Xs[(ty * 4 + i) * 68 + k4 * 4];
            #pragma unroll
            for (int j = 0; j < 4; j++) {
                float4 w = __ldg(&Wv[(k4 * 4 + j) * 16 + tx]);
                u64 w01 = pk2(w.x, w.y);
                u64 w23 = pk2(w.z, w.w);
                #pragma unroll
                for (int i = 0; i < 4; i++) {
                    float xs = (j == 0) ? xv[i].x : (j == 1) ? xv[i].y : (j == 2) ? xv[i].z : xv[i].w;
                    u64 xd = pk2(xs, xs);
                    fma2(t01[i], xd, w01);
                    fma2(t23[i], xd, w23);
                }
            }
        }
        float4 b = __ldg(&((const float4*)bias)[tx]);
        __syncthreads();               // done reading old Xs
        #pragma unroll
        for (int i = 0; i < 4; i++) {
            int gr = r0 + ty * 4 + i;
            float s = 1.0f;
            if (use_dis) s = (gr < n) ? g_dis[gr] : 0.f;
            float4 a;
            unpk2(t01[i], a.x, a.y);
            unpk2(t23[i], a.z, a.w);
            a.x = fmaxf(fmaf(s, a.x, b.x), 0.f);
            a.y = fmaxf(fmaf(s, a.y, b.y), 0.f);
            a.z = fmaxf(fmaf(s, a.z, b.z), 0.f);
            a.w = fmaxf(fmaf(s, a.w, b.w), 0.f);
            *(float4*)&Xs[(ty * 4 + i) * 68 + tx * 4] = a;
        }
    };

    auto cls_accum = [&](int c) {
        if (tx < 10) {
            #pragma unroll
            for (int k4 = 0; k4 < 16; k4++) {
                float4 xv[4];
                #pragma unroll
                for (int i = 0; i < 4; i++)
                    xv[i] = *(const float4*)&Xs[(ty * 4 + i) * 68 + k4 * 4];
                #pragma unroll
                for (int j = 0; j < 4; j++) {
                    float4 w = Wcs[(c * 64 + k4 * 4 + j) * 10 + tx];
                    u64 w01 = pk2(w.x, w.y);
                    u64 w23 = pk2(w.z, w.w);
                    #pragma unroll
                    for (int i = 0; i < 4; i++) {
                        float xs = (j == 0) ? xv[i].x : (j == 1) ? xv[i].y : (j == 2) ? xv[i].z : xv[i].w;
                        u64 xd = pk2(xs, xs);
                        fma2(c01[i], xd, w01);
                        fma2(c23[i], xd, w23);
                    }
                }
            }
        }
    };

    // phase 0: ego = relu(x @ Wego + bego)
    load_tile(x);
    __syncthreads();
    transform(Wego, bego, false);
    __syncthreads();
    cls_accum(0);
    __syncthreads();

    // phase 1: h1 (materialized)
    load_tile(h1);
    __syncthreads();
    cls_accum(1);
    __syncthreads();

    // phase 2: h2 = relu(dis*(y2 @ Wc1) + b1)
    load_tile(y2);
    __syncthreads();
    transform(Wc1, bc1, true);
    __syncthreads();
    cls_accum(2);

    if (tx < 10) {
        float4 b = ((const float4*)bcls)[tx];
        #pragma unroll
        for (int i = 0; i < 4; i++) {
            int gr = r0 + ty * 4 + i;
            if (gr >= n) continue;
            float4 a;
            unpk2(c01[i], a.x, a.y);
            unpk2(c23[i], a.z, a.w);
            a.x += b.x; a.y += b.y; a.z += b.z; a.w += b.w;
            *(float4*)(out + (size_t)gr * CC + tx * 4) = a;
        }
    }
}

// ---------------- launch -----------------------------------------------------
extern "C" void kernel_launch(void* const* d_in, const int* in_sizes, int n_in,
                              void* d_out, int out_size)
{
    const float* x      = (const float*)d_in[0];
    const void*  ei     = d_in[1];
    const float* W_ego  = (const float*)d_in[2];
    const float* b_ego  = (const float*)d_in[3];
    const float* W_conv = (const float*)d_in[4];   // [2, 64, 64]
    const float* b_conv = (const float*)d_in[5];   // [2, 64]
    const float* W_cls  = (const float*)d_in[6];   // [192, 40]
    const float* b_cls  = (const float*)d_in[7];   // [40]

    const int N = in_sizes[0] / DH;
    const int E = in_sizes[1] / 2;

    float *y, *h1, *z;
    cudaGetSymbolAddress((void**)&y,  g_y);
    cudaGetSymbolAddress((void**)&h1, g_h1);
    cudaGetSymbolAddress((void**)&z,  g_z);

    const int T = 256;
    const int NB = (N + T - 1) / T;
    const int EB2 = ((E + 1) / 2 + T - 1) / T;
    const dim3 gb(16, 16);
    const int tile_blocks = (N + 63) / 64;
    const int agg_blocks = (int)(((long long)N * 32 + T - 1) / T);
    const int pre_blocks = (int)(((long long)N * 16 + T - 1) / T);

    // ELL build + fused dis/prescale
    k_init       <<<NB, T>>>(ei, N);
    k_fill       <<<EB2, T>>>(ei, E);
    k_disprescale<<<pre_blocks, T>>>(x, N);

    // hop 1: y1 = z_self + gather(z);  h1 = relu(dis*(y1@Wc0)+b0); z = dis*h1
    k_agg   <<<agg_blocks, T>>>(z, y, N);
    k_gemm_h<<<tile_blocks, gb>>>(y, W_conv, b_conv, h1, N);

    // hop 2: y2 = z_self + gather(z)
    k_agg   <<<agg_blocks, T>>>(z, y, N);

    // fused classifier
    k_cls<<<tile_blocks, gb>>>(x, h1, y,
                               W_ego, b_ego,
                               W_conv + DH * DH, b_conv + DH,
                               W_cls, b_cls, (float*)d_out, N);
}